// round 14
// baseline (speedup 1.0000x reference)
#include <cuda_runtime.h>
#include <cuda_bf16.h>
#include <math.h>

#define BZ 32
#define SZ 128
#define HZ 768
#define MH_ 6
#define KK 4
#define NQ 8      // phase blocks per batch
#define RPB 16    // rows per phase block

__constant__ float c_inv[8] = {1.f, 1.f/2.f, 1.f/3.f, 1.f/4.f, 1.f/5.f, 1.f/6.f, 1.f/7.f, 1.f/8.f};

__device__ float g_dots[BZ * 2 * SZ];   // [b][type][s]: 0=target(wt),1=holder(wh)
__device__ unsigned int g_tick[BZ];     // zero-init; tail resets

#define CE(x, y) { unsigned long long _a = (x), _b = (y); (x) = _a > _b ? _a : _b; (y) = _a > _b ? _b : _a; }

#define WARP_MERGE4(k0, k1, k2, k3)                                            \
    _Pragma("unroll")                                                          \
    for (int off = 16; off; off >>= 1) {                                       \
        unsigned long long o0 = __shfl_xor_sync(0xFFFFFFFFu, k0, off);         \
        unsigned long long o1 = __shfl_xor_sync(0xFFFFFFFFu, k1, off);         \
        unsigned long long o2 = __shfl_xor_sync(0xFFFFFFFFu, k2, off);         \
        unsigned long long o3 = __shfl_xor_sync(0xFFFFFFFFu, k3, off);         \
        unsigned long long c0 = k0 > o3 ? k0 : o3;                             \
        unsigned long long c1 = k1 > o2 ? k1 : o2;                             \
        unsigned long long c2 = k2 > o1 ? k2 : o1;                             \
        unsigned long long c3 = k3 > o0 ? k3 : o0;                             \
        CE(c0, c2); CE(c1, c3); CE(c0, c1); CE(c2, c3);                        \
        k0 = c0; k1 = c1; k2 = c2; k3 = c3;                                    \
    }

// out layout (floats): implicit[0,512) explicit[512,2560) hs[2560,35328) ts[35328,68096)

__global__ __launch_bounds__(512) void k_all(
    const float* __restrict__ emb,
    const int* __restrict__ mask,
    const float* __restrict__ wh,
    const float* __restrict__ bh_,
    const float* __restrict__ wt,
    const float* __restrict__ bt_,
    const float* __restrict__ wi,
    const float* __restrict__ bi,
    const float* __restrict__ we,
    const float* __restrict__ be,
    float* __restrict__ out)
{
    // one 48KB union buffer:
    //  phase blocks: 16 rows x 3072 B row data
    //  tail blocks:  sdot[2][136] @0, cand[2][32] @1280, topv @1792, topi @1824,
    //                partial[16][8] @1856, sbias[8] @2368, s_len @2400, s_bh @2404, s_bt @2408
    __shared__ __align__(16) unsigned char sbuf[49152];

    const int bid = blockIdx.x;
    const int tid = threadIdx.x;
    const int warp = tid >> 5, lane = tid & 31;

    if (bid < BZ * NQ) {
        // ================= PHASE BLOCK (b, q): 16 rows via cp.async ========
        const int b = bid >> 3, q = bid & 7;
        const int r0 = q * RPB;
        const float* eb = emb + b * (SZ * HZ);

        // weights into registers (L2-resident after first wave)
        float4 wh4[6], wt4[6];
#pragma unroll
        for (int i = 0; i < 6; i++) {
            wh4[i] = ((const float4*)wh)[lane + 32 * i];
            wt4[i] = ((const float4*)wt)[lane + 32 * i];
        }

        // 48KB contiguous burst: rows r0..r0+15 (16 x 3072 B)
        {
            const char* gsrc = (const char*)(eb + r0 * HZ);
            unsigned sbase = (unsigned)__cvta_generic_to_shared(sbuf);
#pragma unroll
            for (int i = 0; i < 6; i++) {
                int c = (tid + 512 * i) * 16;
                asm volatile("cp.async.ca.shared.global [%0], [%1], 16;\n"
                             :: "r"(sbase + c), "l"(gsrc + c));
            }
            asm volatile("cp.async.commit_group;\n" ::: "memory");
            asm volatile("cp.async.wait_group 0;\n" ::: "memory");
        }
        __syncthreads();

        // warp w computes row w's dots from smem
        {
            const float4* rp = (const float4*)(sbuf + warp * 3072);
            float ah = 0.f, at = 0.f;
#pragma unroll
            for (int i = 0; i < 6; i++) {
                float4 v = rp[lane + 32 * i];
                ah += v.x * wh4[i].x + v.y * wh4[i].y + v.z * wh4[i].z + v.w * wh4[i].w;
                at += v.x * wt4[i].x + v.y * wt4[i].y + v.z * wt4[i].z + v.w * wt4[i].w;
            }
#pragma unroll
            for (int off = 16; off; off >>= 1) {
                ah += __shfl_xor_sync(0xFFFFFFFFu, ah, off);
                at += __shfl_xor_sync(0xFFFFFFFFu, at, off);
            }
            if (lane == 0) {
                g_dots[b * 256 + (r0 + warp)]       = at;
                g_dots[b * 256 + 128 + (r0 + warp)] = ah;
            }
        }
        __threadfence();
        __syncthreads();
        if (tid == 0) atomicAdd(&g_tick[b], 1u);
        return;
    }

    // ================= TAIL BLOCK (one per batch) ==========================
    {
        const int b = bid - BZ * NQ;
        const float* eb = emb + b * (SZ * HZ);
        float* sdotp  = (float*)sbuf;                                 // [2][136]
        unsigned long long* cand = (unsigned long long*)(sbuf + 1280);// [2][32]
        float* topv   = (float*)(sbuf + 1792);                        // [2][4]
        int*   topi   = (int*)(sbuf + 1824);                          // [2][4]
        float* partial = (float*)(sbuf + 1856);                       // [16][8]
        float* sbias  = (float*)(sbuf + 2368);                        // 8
        int*   ps_len = (int*)(sbuf + 2400);
        float* ps_bh  = (float*)(sbuf + 2404);
        float* ps_bt  = (float*)(sbuf + 2408);

        // scalars + mask length while phase blocks run
        if (tid < 4)            sbias[tid] = bi[tid];
        else if (tid < 8)       sbias[tid] = be[tid - 4];
        if (tid == 8)  *ps_bh = bh_[0];
        if (tid == 9)  *ps_bt = bt_[0];
        if (warp == 13) {
            int4 mv = ((const int4*)(mask + b * SZ))[lane];
            int v = mv.x + mv.y + mv.z + mv.w;
#pragma unroll
            for (int off = 16; off; off >>= 1) v += __shfl_xor_sync(0xFFFFFFFFu, v, off);
            if (lane == 0) *ps_len = v;
        }

        // spin until all NQ phase blocks of this batch have arrived
        if (tid == 0) {
            while (*(volatile unsigned*)&g_tick[b] < (unsigned)NQ) __nanosleep(64);
            g_tick[b] = 0;   // reset for next graph replay
        }
        __syncthreads();
        __threadfence();     // acquire: order g_dots reads after the flag

        // load full-batch row dots into smem (+ zero pads)
        if (tid < 256) sdotp[(tid >> 7) * 136 + (tid & 127)] = g_dots[b * 256 + tid];
        else if (tid < 272) {
            int t2 = tid - 256;
            sdotp[(t2 >> 3) * 136 + 128 + (t2 & 7)] = 0.f;
        }
        __syncthreads();

        // scores: warp = type*8 + width m; 4 starts per lane; bitonic top-4
        {
            const int type = warp >> 3;
            const int m = warp & 7;
            const int len = *ps_len;
            const float bias = type ? *ps_bh : *ps_bt;
            const float invw = c_inv[m];
            const float* sd = sdotp + type * 136;
            unsigned long long K[4];
#pragma unroll
            for (int ii = 0; ii < 4; ii++) {
                int s = lane + 32 * ii;
                float sum = 0.f;
                for (int r = 0; r <= m; r++) sum += sd[s + r];
                bool valid = ((s + m) < len) && (type == 0 || m < MH_);
                float v = valid ? 1.f / (1.f + __expf(-(sum * invw + bias))) : -1.f;
                int gidx = m * SZ + s;
                out[(type ? 2560 : 35328) + b * 1024 + gidx] = v;
                unsigned u = __float_as_uint(v);
                u = (u & 0x80000000u) ? ~u : (u | 0x80000000u);
                K[ii] = ((unsigned long long)u << 32) | (unsigned)(0xFFFFFFFFu - gidx);
            }
            CE(K[0], K[1]); CE(K[2], K[3]);
            CE(K[0], K[2]); CE(K[1], K[3]);
            CE(K[1], K[2]);
            WARP_MERGE4(K[0], K[1], K[2], K[3]);
            if (lane == 0) {
#pragma unroll
                for (int k = 0; k < KK; k++) cand[type * 32 + m * 4 + k] = K[k];
            }
        }
        __syncthreads();

        // merge 32 -> 4 per type (warp0 targets, warp1 holders)
        if (warp < 2) {
            unsigned long long k0 = cand[warp * 32 + lane];
            unsigned long long k1 = 0ull, k2 = 0ull, k3 = 0ull;
            WARP_MERGE4(k0, k1, k2, k3);
            if (lane == 0) {
                unsigned long long ks[4] = {k0, k1, k2, k3};
#pragma unroll
                for (int k = 0; k < KK; k++) {
                    unsigned hi = (unsigned)(ks[k] >> 32);
                    unsigned lo = (unsigned)ks[k];
                    float v = (hi & 0x80000000u) ? __uint_as_float(hi ^ 0x80000000u)
                                                 : __uint_as_float(~hi);
                    topv[warp * KK + k] = v;
                    topi[warp * KK + k] = (int)(0xFFFFFFFFu - lo);
                }
            }
        }
        __syncthreads();

        // rep dots: 2 warps per span (warps 0-7 target, 8-15 holder)
        {
            const int type = warp >> 3;
            const int span = (warp >> 1) & 3;
            const int half = warp & 1;
            const int idx = topi[type * KK + span];
            const bool valid = topv[type * KK + span] > 0.f;
            const int m = idx >> 7, s = idx & 127;
            const float invw = c_inv[m];
            const float4* wi4 = (const float4*)wi;
            const float4* we4 = (const float4*)we;

            float acc[8] = {0.f,0.f,0.f,0.f,0.f,0.f,0.f,0.f};
            if (valid) {
                float4 sum[3];
#pragma unroll
                for (int i = 0; i < 3; i++) sum[i] = make_float4(0.f,0.f,0.f,0.f);
                const int c0 = lane + 96 * half;
#pragma unroll
                for (int r = 0; r < 8; r++) {
                    if (r <= m) {
                        const float4* rp = (const float4*)(eb + (s + r) * HZ);
#pragma unroll
                        for (int i = 0; i < 3; i++) {
                            float4 a = rp[c0 + 32 * i];
                            sum[i].x += a.x; sum[i].y += a.y;
                            sum[i].z += a.z; sum[i].w += a.w;
                        }
                    }
                }
#pragma unroll
                for (int i = 0; i < 3; i++) {
                    int h4 = c0 + 32 * i;
                    float sv[4] = {sum[i].x * invw, sum[i].y * invw,
                                   sum[i].z * invw, sum[i].w * invw};
#pragma unroll
                    for (int j = 0; j < 4; j++) {
                        int f = 4 * h4 + j;
                        if (type == 0) {
                            float4 wv = wi4[f];
                            acc[0] += sv[j] * wv.x; acc[1] += sv[j] * wv.y;
                            acc[2] += sv[j] * wv.z; acc[3] += sv[j] * wv.w;
                            float4 ev = we4[HZ + f];
                            acc[4] += sv[j] * ev.x; acc[5] += sv[j] * ev.y;
                            acc[6] += sv[j] * ev.z; acc[7] += sv[j] * ev.w;
                        } else {
                            float4 ev = we4[f];
                            acc[0] += sv[j] * ev.x; acc[1] += sv[j] * ev.y;
                            acc[2] += sv[j] * ev.z; acc[3] += sv[j] * ev.w;
                        }
                    }
                }
            }
#pragma unroll
            for (int off = 16; off; off >>= 1)
#pragma unroll
                for (int j = 0; j < 8; j++)
                    acc[j] += __shfl_xor_sync(0xFFFFFFFFu, acc[j], off);
            if (lane == 0) {
#pragma unroll
                for (int j = 0; j < 8; j++) partial[warp * 8 + j] = acc[j];
            }
        }
        __syncthreads();

        // logits
        if (tid < 64) {
            int k = tid >> 4, i = (tid >> 2) & 3, j = tid & 3;
            bool pv = (topv[KK + k] > 0.f) && (topv[i] > 0.f);
            float val = sbias[4 + j];
            if (pv) val += partial[(8 + 2*k) * 8 + j] + partial[(8 + 2*k + 1) * 8 + j]
                         + partial[(2*i) * 8 + 4 + j] + partial[(2*i + 1) * 8 + 4 + j];
            out[512 + b * 64 + tid] = val;
        } else if (tid < 80) {
            int t2 = tid - 64;
            int i = t2 >> 2, j = t2 & 3;
            float val = sbias[j];
            if (topv[i] > 0.f) val += partial[(2*i) * 8 + j] + partial[(2*i + 1) * 8 + j];
            out[b * 16 + t2] = val;
        }
    }
}

extern "C" void kernel_launch(void* const* d_in, const int* in_sizes, int n_in,
                              void* d_out, int out_size)
{
    const float* emb = (const float*)d_in[0];
    const int*   msk = (const int*)d_in[1];
    const float* wh  = (const float*)d_in[2];
    const float* bh  = (const float*)d_in[3];
    const float* wt  = (const float*)d_in[4];
    const float* bt  = (const float*)d_in[5];
    const float* wi  = (const float*)d_in[6];
    const float* bi  = (const float*)d_in[7];
    const float* we  = (const float*)d_in[8];
    const float* be  = (const float*)d_in[9];
    float* out = (float*)d_out;

    k_all<<<BZ * NQ + BZ, 512>>>(emb, msk, wh, bh, wt, bt, wi, bi, we, be, out);
}